// round 1
// baseline (speedup 1.0000x reference)
#include <cuda_runtime.h>
#include <cuda_bf16.h>
#include <math.h>

// Problem constants
#define B    64
#define C    256
#define S    3136          // 56*56
#define S4   784           // S/4
#define HID  196
#define KSEL 1568          // rank of first KEPT element (0-indexed kth smallest)

// K-split for GEMM1
#define KC   32
#define KCH  98            // 3136/32

// Scratch (device globals: no allocation allowed)
__device__ float g_Y[B * S];            // pooled means          [64,3136]
__device__ float g_Hpart[KC * B * HID]; // GEMM1 partials        [32][64*196]
__device__ float g_H[B * HID];          // relu(hidden)          [64,196]
__device__ float g_S[B * S];            // sigmoid outputs       [64,3136]
__device__ float g_M[B * S];            // masked row            [64,3136]

// ---------------------------------------------------------------------------
// K1: channel-mean pool.  Y[b][s] = mean_c x[b][c][s].  float4 coalesced.
// grid (4, 64), block 256
// ---------------------------------------------------------------------------
__global__ void k_pool(const float* __restrict__ x) {
    int b = blockIdx.y;
    int f = blockIdx.x * blockDim.x + threadIdx.x;   // float4 index 0..783
    if (f >= S4) return;
    const float4* xp = reinterpret_cast<const float4*>(x) + (size_t)b * C * S4 + f;
    float sx = 0.f, sy = 0.f, sz = 0.f, sw = 0.f;
#pragma unroll 8
    for (int c = 0; c < C; c++) {
        float4 v = __ldg(xp + (size_t)c * S4);
        sx += v.x; sy += v.y; sz += v.z; sw += v.w;
    }
    const float inv = 1.0f / (float)C;
    float4 o; o.x = sx * inv; o.y = sy * inv; o.z = sz * inv; o.w = sw * inv;
    reinterpret_cast<float4*>(g_Y)[(size_t)b * S4 + f] = o;
}

// ---------------------------------------------------------------------------
// K2: GEMM1 partials.  Hpart[kc][b][o] = sum_{j in chunk kc} Y[b][j]*W1[o][j]
// grid (KC=32, 7 o-tiles of 28), block 256.  W1 read exactly once total.
// ---------------------------------------------------------------------------
__global__ void k_gemm1(const float* __restrict__ W1) {
    __shared__ __align__(16) float sY[B * 100];      // [b][j] pitch 100
    __shared__ __align__(16) float sW[KCH * 28];     // [j][o_local]
    int kc = blockIdx.x;
    int ob = blockIdx.y;                // 0..6 -> o base = ob*28
    int kb = kc * KCH;
    int t = threadIdx.x;

    for (int idx = t; idx < B * KCH; idx += 256) {
        int j = idx % KCH, b2 = idx / KCH;
        sY[b2 * 100 + j] = g_Y[b2 * S + kb + j];
    }
    for (int idx = t; idx < KCH * 28; idx += 256) {
        int j = idx % KCH, o = idx / KCH;
        sW[j * 28 + o] = W1[(size_t)(ob * 28 + o) * S + kb + j];
    }
    __syncthreads();

    for (int p = t; p < 448; p += 256) {             // 64 b x 7 o-quads
        int og = p % 7, b2 = p / 7;
        float a0 = 0.f, a1 = 0.f, a2 = 0.f, a3 = 0.f;
        const float* yr = &sY[b2 * 100];
#pragma unroll 7
        for (int j = 0; j < KCH; j++) {
            float yv = yr[j];
            float4 w = *reinterpret_cast<const float4*>(&sW[j * 28 + og * 4]);
            a0 = fmaf(yv, w.x, a0); a1 = fmaf(yv, w.y, a1);
            a2 = fmaf(yv, w.z, a2); a3 = fmaf(yv, w.w, a3);
        }
        int oG = ob * 28 + og * 4;
        float4 r; r.x = a0; r.y = a1; r.z = a2; r.w = a3;
        reinterpret_cast<float4*>(g_Hpart)[(kc * (B * HID) + b2 * HID + oG) >> 2] = r;
    }
}

// ---------------------------------------------------------------------------
// K3: reduce partials + ReLU.  grid 49, block 256 (exactly 12544 outputs)
// ---------------------------------------------------------------------------
__global__ void k_redrelu() {
    int idx = blockIdx.x * 256 + threadIdx.x;
    if (idx >= B * HID) return;
    float s = 0.f;
#pragma unroll
    for (int kc = 0; kc < KC; kc++) s += g_Hpart[kc * (B * HID) + idx];
    g_H[idx] = s > 0.f ? s : 0.f;
}

// ---------------------------------------------------------------------------
// K4: GEMM2 + sigmoid.  S[b][n] = sigmoid( sum_j H[b][j]*W2[n][j] )
// grid (112 n-tiles of 28, 2 b-halves of 32), block 256.  W2 read twice total.
// ---------------------------------------------------------------------------
__global__ void k_gemm2(const float* __restrict__ W2) {
    __shared__ __align__(16) float sH[32 * 200];     // [b][j] pitch 200
    __shared__ __align__(16) float sW2[HID * 28];    // [j][n_local]
    int nt = blockIdx.x;
    int b0 = blockIdx.y * 32;
    int t = threadIdx.x;

    for (int idx = t; idx < 32 * HID; idx += 256) {
        int j = idx % HID, b2 = idx / HID;
        sH[b2 * 200 + j] = g_H[(b0 + b2) * HID + j];
    }
    for (int idx = t; idx < HID * 28; idx += 256) {
        int j = idx % HID, nl = idx / HID;
        sW2[j * 28 + nl] = W2[(size_t)(nt * 28 + nl) * HID + j];
    }
    __syncthreads();

    if (t < 224) {                                   // 32 b x 7 n-quads
        int ng = t % 7, b2 = t / 7;
        float a0 = 0.f, a1 = 0.f, a2 = 0.f, a3 = 0.f;
        const float* hr = &sH[b2 * 200];
#pragma unroll 4
        for (int j = 0; j < HID; j++) {
            float hv = hr[j];
            float4 w = *reinterpret_cast<const float4*>(&sW2[j * 28 + ng * 4]);
            a0 = fmaf(hv, w.x, a0); a1 = fmaf(hv, w.y, a1);
            a2 = fmaf(hv, w.z, a2); a3 = fmaf(hv, w.w, a3);
        }
        float4 r;
        r.x = 1.0f / (1.0f + expf(-a0));
        r.y = 1.0f / (1.0f + expf(-a1));
        r.z = 1.0f / (1.0f + expf(-a2));
        r.w = 1.0f / (1.0f + expf(-a3));
        int nG = nt * 28 + ng * 4;
        *reinterpret_cast<float4*>(&g_S[(size_t)(b0 + b2) * S + nG]) = r;
    }
}

// ---------------------------------------------------------------------------
// K5: exact rank-1568 selection per row + masking (stable-argsort semantics).
// All values are sigmoid outputs (>0), so unsigned bit order == value order.
// 4-pass radix select with parallel bin scan; tie-break = ascending index.
// grid 64, block 256
// ---------------------------------------------------------------------------
__global__ void k_select() {
    __shared__ float sv[S];
    __shared__ unsigned int hist[256];
    __shared__ unsigned int scn[256];
    __shared__ unsigned int sh_pref, sh_r, sh_base;
    int b = blockIdx.x, t = threadIdx.x;

    for (int i = t; i < S; i += 256) sv[i] = g_S[b * S + i];
    if (t == 0) { sh_pref = 0u; sh_r = KSEL; sh_base = 0u; }
    __syncthreads();

    // radix select: find bit pattern T of the KSEL-th smallest value
    for (int shift = 24; shift >= 0; shift -= 8) {
        hist[t] = 0u;
        __syncthreads();
        unsigned pref = sh_pref;
        unsigned r    = sh_r;
        unsigned hm   = (shift == 24) ? 0u : (0xFFFFFFFFu << (shift + 8));
        for (int i = t; i < S; i += 256) {
            unsigned u = __float_as_uint(sv[i]);
            if ((u & hm) == pref) atomicAdd(&hist[(u >> shift) & 255], 1u);
        }
        __syncthreads();
        unsigned v = hist[t];
        scn[t] = v;
        __syncthreads();
        for (int off = 1; off < 256; off <<= 1) {
            unsigned w2 = (t >= off) ? scn[t - off] : 0u;
            __syncthreads();
            scn[t] += w2;
            __syncthreads();
        }
        unsigned excl = scn[t] - v;                  // exclusive prefix
        if (v > 0u && r >= excl && r < scn[t]) {     // exactly one thread
            sh_pref = pref | ((unsigned)t << shift);
            sh_r    = r - excl;
        }
        __syncthreads();
    }
    unsigned T    = sh_pref;   // bits of threshold value (the first KEPT value)
    unsigned rfin = sh_r;      // # of threshold-equal entries (lowest index) to zero

    // mask: zero u<T; among u==T zero the first rfin by ascending index
    for (int start = 0; start < S; start += 256) {
        int i = start + t;
        unsigned u = (i < S) ? __float_as_uint(sv[i]) : 0xFFFFFFFFu;
        unsigned flag = (i < S && u == T) ? 1u : 0u;
        scn[t] = flag;
        __syncthreads();
        for (int off = 1; off < 256; off <<= 1) {
            unsigned w2 = (t >= off) ? scn[t - off] : 0u;
            __syncthreads();
            scn[t] += w2;
            __syncthreads();
        }
        if (i < S) {
            unsigned eqr = sh_base + scn[t] - flag;
            float val = sv[i];
            if (u < T || (flag && eqr < rfin)) val = 0.f;
            g_M[b * S + i] = val;
        }
        __syncthreads();
        if (t == 0) sh_base += scn[255];
        __syncthreads();
    }
}

// ---------------------------------------------------------------------------
// K6: broadcast masked row over 256 planes.  float4 stores, M row L2-resident.
// grid (4, 16384=B*C), block 256
// ---------------------------------------------------------------------------
__global__ void k_bcast(float* __restrict__ out) {
    int plane = blockIdx.y;                          // b*256 + c
    int f = blockIdx.x * blockDim.x + threadIdx.x;   // float4 index
    if (f >= S4) return;
    int b = plane >> 8;
    float4 v = __ldg(reinterpret_cast<const float4*>(g_M) + (size_t)b * S4 + f);
    reinterpret_cast<float4*>(out)[(size_t)plane * S4 + f] = v;
}

// ---------------------------------------------------------------------------
extern "C" void kernel_launch(void* const* d_in, const int* in_sizes, int n_in,
                              void* d_out, int out_size) {
    const float* x  = (const float*)d_in[0];
    const float* W1 = (const float*)d_in[1];
    const float* W2 = (const float*)d_in[2];
    float* out = (float*)d_out;

    k_pool   <<<dim3(4, B),     256>>>(x);
    k_gemm1  <<<dim3(KC, 7),    256>>>(W1);
    k_redrelu<<<49,             256>>>();
    k_gemm2  <<<dim3(112, 2),   256>>>(W2);
    k_select <<<B,              256>>>();
    k_bcast  <<<dim3(4, B * C), 256>>>(out);
}

// round 2
// speedup vs baseline: 1.0464x; 1.0464x over previous
#include <cuda_runtime.h>
#include <cuda_bf16.h>
#include <math.h>

// Problem constants
#define B    64
#define C    256
#define S    3136          // 56*56
#define S4   784           // S/4
#define HID  196
#define KSEL 1568          // rank of first KEPT element (0-indexed kth smallest)

// K-split for GEMM1
#define KC   32
#define KCH  98            // 3136/32

// Scratch (device globals: no allocation allowed)
__device__ float g_Y[B * S];            // pooled means          [64,3136]
__device__ float g_Hpart[KC * B * HID]; // GEMM1 partials        [32][64*196]
__device__ float g_H[B * HID];          // relu(hidden)          [64,196]
__device__ float g_S[B * S];            // sigmoid outputs       [64,3136]
__device__ float g_M[B * S];            // masked row            [64,3136]

// ---------------------------------------------------------------------------
// K1: channel-mean pool.  Y[b][s] = mean_c x[b][c][s].  float4 coalesced.
// grid (4, 64), block 256
// ---------------------------------------------------------------------------
__global__ void k_pool(const float* __restrict__ x) {
    int b = blockIdx.y;
    int f = blockIdx.x * blockDim.x + threadIdx.x;   // float4 index 0..783
    if (f >= S4) return;
    const float4* xp = reinterpret_cast<const float4*>(x) + (size_t)b * C * S4 + f;
    float sx = 0.f, sy = 0.f, sz = 0.f, sw = 0.f;
#pragma unroll 8
    for (int c = 0; c < C; c++) {
        float4 v = __ldg(xp + (size_t)c * S4);
        sx += v.x; sy += v.y; sz += v.z; sw += v.w;
    }
    const float inv = 1.0f / (float)C;
    float4 o; o.x = sx * inv; o.y = sy * inv; o.z = sz * inv; o.w = sw * inv;
    reinterpret_cast<float4*>(g_Y)[(size_t)b * S4 + f] = o;
}

// ---------------------------------------------------------------------------
// K2: GEMM1 partials.  Hpart[kc][b][o] = sum_{j in chunk} Y[b][j]*W1[o][j]
// grid (32 kc, 7 o-tiles of 28), block 256.
// Thread = (b2 = t&63, og = t>>6); each thread accumulates 7 outputs in regs.
// sY pitch 101 -> 32 distinct b2 hit 32 distinct banks (gcd(101%32=5,32)=1).
// sW reads are warp-uniform broadcasts.
// ---------------------------------------------------------------------------
__global__ void k_gemm1(const float* __restrict__ W1) {
    __shared__ float sY[B * 101];        // [b][j]
    __shared__ float sW[KCH * 28];       // [j][o_local]
    int kc = blockIdx.x;
    int ob = blockIdx.y;                 // o base = ob*28
    int kb = kc * KCH;
    int t = threadIdx.x;

    for (int idx = t; idx < B * KCH; idx += 256) {
        int j = idx % KCH, b2 = idx / KCH;
        sY[b2 * 101 + j] = g_Y[b2 * S + kb + j];
    }
    for (int idx = t; idx < KCH * 28; idx += 256) {
        int j = idx % KCH, o = idx / KCH;
        sW[j * 28 + o] = W1[(size_t)(ob * 28 + o) * S + kb + j];
    }
    __syncthreads();

    int b2 = t & 63;
    int og = t >> 6;                     // 0..3, 7 outputs each
    float acc[7];
#pragma unroll
    for (int o = 0; o < 7; o++) acc[o] = 0.f;
#pragma unroll 2
    for (int j = 0; j < KCH; j++) {
        float y = sY[b2 * 101 + j];
        const float* wr = &sW[j * 28 + og * 7];
#pragma unroll
        for (int o = 0; o < 7; o++) acc[o] = fmaf(y, wr[o], acc[o]);
    }
    int base = kc * (B * HID) + b2 * HID + ob * 28 + og * 7;
#pragma unroll
    for (int o = 0; o < 7; o++) g_Hpart[base + o] = acc[o];
}

// ---------------------------------------------------------------------------
// K3: reduce partials + ReLU.  grid 49, block 256
// ---------------------------------------------------------------------------
__global__ void k_redrelu() {
    int idx = blockIdx.x * 256 + threadIdx.x;
    if (idx >= B * HID) return;
    float s = 0.f;
#pragma unroll
    for (int kc = 0; kc < KC; kc++) s += g_Hpart[kc * (B * HID) + idx];
    g_H[idx] = s > 0.f ? s : 0.f;
}

// ---------------------------------------------------------------------------
// K4: GEMM2 + sigmoid.  S[b][n] = sigmoid( sum_j H[b][j]*W2[n][j] )
// grid (98 n-tiles of 32, 4 b-quarters of 16), block 256.
// sW2 pitch 33: conflict-free writes (stride 33) and reads (stride 1).
// sHT transposed [j][b]: float2 broadcast per thread pair of b's.
// ---------------------------------------------------------------------------
__global__ void k_gemm2(const float* __restrict__ W2) {
    __shared__ float sW2[HID * 33];          // [j][n_local]
    __shared__ __align__(8) float sHT[HID * 16];  // [j][b_local]
    int n0 = blockIdx.x * 32;
    int b0 = blockIdx.y * 16;
    int t = threadIdx.x;

    for (int idx = t; idx < HID * 32; idx += 256) {
        int nl = idx / HID, j = idx % HID;       // global read coalesced
        sW2[j * 33 + nl] = W2[(size_t)(n0) * HID + idx];
    }
    for (int idx = t; idx < HID * 16; idx += 256) {
        int b2 = idx & 15, j = idx >> 4;
        sHT[idx] = g_H[(b0 + b2) * HID + j];     // sHT[j*16+b2] == sHT[idx]
    }
    __syncthreads();

    int nl = t & 31;
    int bg = t >> 5;                             // 0..7, 2 b's each
    float a0 = 0.f, a1 = 0.f;
#pragma unroll 4
    for (int j = 0; j < HID; j++) {
        float w = sW2[j * 33 + nl];
        float2 h = *reinterpret_cast<const float2*>(&sHT[j * 16 + bg * 2]);
        a0 = fmaf(h.x, w, a0);
        a1 = fmaf(h.y, w, a1);
    }
    int b = b0 + bg * 2;
    int n = n0 + nl;
    g_S[(size_t)b * S + n]       = 1.0f / (1.0f + expf(-a0));
    g_S[(size_t)(b + 1) * S + n] = 1.0f / (1.0f + expf(-a1));
}

// ---------------------------------------------------------------------------
// K5: exact rank-1568 selection per row + masking (stable-argsort semantics).
// Sigmoid outputs > 0  =>  unsigned bit order == value order.
// 4-pass radix select with warp-shuffle scans; single-pass masking with
// per-thread contiguous segments + one block prefix scan for tie ranks.
// grid 64, block 256
// ---------------------------------------------------------------------------
__global__ void k_select() {
    __shared__ float sv[S];
    __shared__ unsigned int hist[256];
    __shared__ unsigned int wsum[8];
    __shared__ unsigned int sh_pref, sh_r;
    int b = blockIdx.x, t = threadIdx.x;
    int lane = t & 31, wid = t >> 5;

    for (int i = t; i < S; i += 256) sv[i] = g_S[b * S + i];
    if (t == 0) { sh_pref = 0u; sh_r = KSEL; }
    __syncthreads();

    // radix select: find bit pattern T of the KSEL-th smallest value
    for (int shift = 24; shift >= 0; shift -= 8) {
        hist[t] = 0u;
        __syncthreads();
        unsigned pref = sh_pref;
        unsigned r    = sh_r;
        unsigned hm   = (shift == 24) ? 0u : (0xFFFFFFFFu << (shift + 8));
        for (int i = t; i < S; i += 256) {
            unsigned u = __float_as_uint(sv[i]);
            if ((u & hm) == pref) atomicAdd(&hist[(u >> shift) & 255], 1u);
        }
        __syncthreads();
        unsigned v = hist[t];
        unsigned x = v;
#pragma unroll
        for (int off = 1; off < 32; off <<= 1) {
            unsigned y = __shfl_up_sync(0xFFFFFFFFu, x, off);
            if (lane >= off) x += y;
        }
        if (lane == 31) wsum[wid] = x;
        __syncthreads();
        if (t < 8) {
            unsigned s = wsum[t];
#pragma unroll
            for (int off = 1; off < 8; off <<= 1) {
                unsigned y = __shfl_up_sync(0xFFu, s, off);
                if (t >= off) s += y;
            }
            wsum[t] = s;
        }
        __syncthreads();
        unsigned incl = x + (wid ? wsum[wid - 1] : 0u);
        unsigned excl = incl - v;
        if (v > 0u && r >= excl && r < incl) {   // exactly one thread
            sh_pref = pref | ((unsigned)t << shift);
            sh_r    = r - excl;
        }
        __syncthreads();
    }
    unsigned T    = sh_pref;   // bits of threshold (first KEPT value)
    unsigned rfin = sh_r;      // # of threshold-equal entries (lowest idx) to zero

    // masking: zero u<T; among u==T zero the first rfin by ascending index
    int lo = (t * S) >> 8;
    int hi = ((t + 1) * S) >> 8;
    unsigned cnt = 0;
    for (int i = lo; i < hi; i++)
        cnt += (__float_as_uint(sv[i]) == T) ? 1u : 0u;
    unsigned x = cnt;
#pragma unroll
    for (int off = 1; off < 32; off <<= 1) {
        unsigned y = __shfl_up_sync(0xFFFFFFFFu, x, off);
        if (lane >= off) x += y;
    }
    if (lane == 31) wsum[wid] = x;
    __syncthreads();
    if (t < 8) {
        unsigned s = wsum[t];
#pragma unroll
        for (int off = 1; off < 8; off <<= 1) {
            unsigned y = __shfl_up_sync(0xFFu, s, off);
            if (t >= off) s += y;
        }
        wsum[t] = s;
    }
    __syncthreads();
    unsigned e = x - cnt + (wid ? wsum[wid - 1] : 0u);  // exclusive prefix
    for (int i = lo; i < hi; i++) {
        unsigned u = __float_as_uint(sv[i]);
        float val = sv[i];
        if (u < T) val = 0.f;
        else if (u == T) { if (e < rfin) val = 0.f; e++; }
        g_M[b * S + i] = val;
    }
}

// ---------------------------------------------------------------------------
// K6: broadcast masked row over 256 planes.  One load, 256 float4 stores.
// grid 196, block 256  (196*256 == 64*784 exactly)
// ---------------------------------------------------------------------------
__global__ void k_bcast(float* __restrict__ out) {
    int idx = blockIdx.x * 256 + threadIdx.x;
    int b = idx / S4;
    int f = idx % S4;
    float4 v = __ldg(reinterpret_cast<const float4*>(g_M) + (size_t)b * S4 + f);
    float4* o = reinterpret_cast<float4*>(out) + (size_t)b * C * S4 + f;
#pragma unroll 8
    for (int c = 0; c < C; c++) {
        o[(size_t)c * S4] = v;
    }
}

// ---------------------------------------------------------------------------
extern "C" void kernel_launch(void* const* d_in, const int* in_sizes, int n_in,
                              void* d_out, int out_size) {
    const float* x  = (const float*)d_in[0];
    const float* W1 = (const float*)d_in[1];
    const float* W2 = (const float*)d_in[2];
    float* out = (float*)d_out;

    k_pool   <<<dim3(4, B),   256>>>(x);
    k_gemm1  <<<dim3(KC, 7),  256>>>(W1);
    k_redrelu<<<49,           256>>>();
    k_gemm2  <<<dim3(98, 4),  256>>>(W2);
    k_select <<<B,            256>>>();
    k_bcast  <<<196,          256>>>(out);
}